// round 5
// baseline (speedup 1.0000x reference)
#include <cuda_runtime.h>
#include <cuda_bf16.h>
#include <cstdint>

#define MAXN 50000
#define MAXE 800000
#define H 64
#define HC 16   // H/4 float4 chunks
#define EPS 1e-5f

// ------------------------- device scratch (no allocs allowed) -------------------------
__device__ __align__(256) float g_bufA[MAXN * H];   // layer output y (agg result)
__device__ __align__(256) float g_bufB[MAXN * H];   // hs = (act @ W^T) * dinv
__device__ int   g_degcnt[MAXN];
__device__ int   g_rowptr[MAXN + 1];
__device__ int   g_cursor[MAXN];
__device__ int   g_csrsrc[MAXE];
__device__ float g_dinv[MAXN];
__device__ float g_sum[3 * H];     // per-layer BN stats
__device__ float g_sumsq[3 * H];
__device__ float g_pool[64 * H];
__device__ int   g_bsum[1024];

// ------------------------- utility kernels -------------------------
__global__ void zero_all_kernel(int n) {
    int i = blockIdx.x * blockDim.x + threadIdx.x;
    int stride = gridDim.x * blockDim.x;
    for (int t = i; t < n; t += stride) g_degcnt[t] = 0;
    if (i < 64 * H) g_pool[i] = 0.f;
    if (i < 3 * H) { g_sum[i] = 0.f; g_sumsq[i] = 0.f; }
}

__global__ void hist_kernel(const int* __restrict__ ei, int e) {
    int i = blockIdx.x * blockDim.x + threadIdx.x;
    int stride = gridDim.x * blockDim.x;
    for (int t = i; t < e; t += stride) {
        int dst = ei[e + t];
        atomicAdd(&g_degcnt[dst], 1);
    }
}

// block-wide inclusive scan for 1024 threads
__device__ __forceinline__ int block_incl_scan(int v, int tid) {
    __shared__ int ws[32];
    int lane = tid & 31, w = tid >> 5;
    #pragma unroll
    for (int o = 1; o < 32; o <<= 1) {
        int t = __shfl_up_sync(0xffffffffu, v, o);
        if (lane >= o) v += t;
    }
    if (lane == 31) ws[w] = v;
    __syncthreads();
    if (w == 0) {
        int s = ws[lane];
        #pragma unroll
        for (int o = 1; o < 32; o <<= 1) {
            int t = __shfl_up_sync(0xffffffffu, s, o);
            if (lane >= o) s += t;
        }
        ws[lane] = s;
    }
    __syncthreads();
    return v + (w > 0 ? ws[w - 1] : 0);
}

__global__ void scanA_kernel(int n) {
    int tid = threadIdx.x;
    int gid = blockIdx.x * 1024 + tid;
    int v = (gid < n) ? g_degcnt[gid] : 0;
    int incl = block_incl_scan(v, tid);
    if (gid < n) g_rowptr[gid] = incl - v;   // exclusive within block
    if (tid == 1023) g_bsum[blockIdx.x] = incl;
}

__global__ void scanB_kernel(int nb) {
    int tid = threadIdx.x;
    int v = (tid < nb) ? g_bsum[tid] : 0;
    int incl = block_incl_scan(v, tid);
    if (tid < nb) g_bsum[tid] = incl - v;    // exclusive block offsets
}

__global__ void scanC_kernel(int n, int e) {
    int tid = threadIdx.x;
    int gid = blockIdx.x * 1024 + tid;
    if (gid < n) {
        int r = g_rowptr[gid] + g_bsum[blockIdx.x];
        g_rowptr[gid] = r;
        g_cursor[gid] = r;
        g_dinv[gid] = rsqrtf((float)g_degcnt[gid] + 1.0f);
    }
    if (gid == 0) g_rowptr[n] = e;
}

__global__ void fill_csr_kernel(const int* __restrict__ ei, int e) {
    int i = blockIdx.x * blockDim.x + threadIdx.x;
    int stride = gridDim.x * blockDim.x;
    for (int t = i; t < e; t += stride) {
        int s = ei[t];
        int d = ei[e + t];
        int pos = atomicAdd(&g_cursor[d], 1);
        g_csrsrc[pos] = s;
    }
}

// ------------------------- GEMM: hs = act @ W^T, scaled by dinv -------------------------
// Block = 256 threads = 8 warps, each warp computes 4 rows x 64 cols.
// W stored transposed in smem (stride 65, conflict-free).
// BN: input element = relu(in*scale[k]+shift[k]); scale/shift computed inline from
// per-layer stats (replaces the separate finalize kernel).
template <int K, bool BN, bool FROMX>
__global__ void __launch_bounds__(256) gemm_kernel(const float* __restrict__ in,
                                                   const float* __restrict__ W,
                                                   const float* __restrict__ gamma,
                                                   const float* __restrict__ beta,
                                                   int n, int layer, float fn) {
    __shared__ float Wsm[K * 65];
    __shared__ float sScale[H], sShift[H];
    int tid = threadIdx.x;
    for (int idx = tid; idx < H * K; idx += 256) {
        int o = idx / K, k = idx - o * K;
        Wsm[k * 65 + o] = W[idx];
    }
    if (BN && tid < H) {
        float m = g_sum[layer * H + tid] / fn;
        float var = g_sumsq[layer * H + tid] / fn - m * m;
        float inv = rsqrtf(var + EPS);
        float sc = inv * gamma[tid];
        sScale[tid] = sc;
        sShift[tid] = beta[tid] - m * sc;
    }
    __syncthreads();

    const float* src = FROMX ? in : g_bufA;

    int warp = tid >> 5, lane = tid & 31;
    int row0 = (blockIdx.x * 8 + warp) * 4;

    constexpr int J = K / 32;
    float a[4][J];
    #pragma unroll
    for (int r = 0; r < 4; r++) {
        int row = row0 + r;
        #pragma unroll
        for (int j = 0; j < J; j++) {
            int k = lane + 32 * j;
            float v = 0.f;
            if (row < n) {
                v = src[(size_t)row * K + k];
                if (BN) v = fmaxf(fmaf(v, sScale[k], sShift[k]), 0.f);
            }
            a[r][j] = v;
        }
    }

    float acc[4][2];
    #pragma unroll
    for (int r = 0; r < 4; r++) { acc[r][0] = 0.f; acc[r][1] = 0.f; }

    #pragma unroll
    for (int j = 0; j < J; j++) {
        #pragma unroll
        for (int ks = 0; ks < 32; ks++) {
            int kk = j * 32 + ks;
            float w0 = Wsm[kk * 65 + lane];
            float w1 = Wsm[kk * 65 + lane + 32];
            #pragma unroll
            for (int r = 0; r < 4; r++) {
                float av = __shfl_sync(0xffffffffu, a[r][j], ks);
                acc[r][0] = fmaf(av, w0, acc[r][0]);
                acc[r][1] = fmaf(av, w1, acc[r][1]);
            }
        }
    }

    #pragma unroll
    for (int r = 0; r < 4; r++) {
        int row = row0 + r;
        if (row < n) {
            float dv = g_dinv[row];
            g_bufB[(size_t)row * H + lane]      = acc[r][0] * dv;
            g_bufB[(size_t)row * H + lane + 32] = acc[r][1] * dv;
        }
    }
}

// ------------------------- Aggregation: y = dinv*(sum_nbr hs + hs_self) + bias ------------
// Warp per node; FOUR quarter-warp edge streams (8 lanes x 2 float4 = 256B row each),
// one-iteration index prefetch, 2-level shfl reduction. Stats accumulated per layer.
__global__ void __launch_bounds__(256) agg_kernel(const float* __restrict__ bias,
                                                  int n, int layer) {
    int tid = threadIdx.x;
    int gw = (blockIdx.x * blockDim.x + tid) >> 5;
    int nw = (gridDim.x * blockDim.x) >> 5;
    int lane = tid & 31;
    int qid = lane >> 3;          // quarter-warp id 0..3 (edge stream)
    int q8  = lane & 7;           // lane within quarter: columns q8*8 .. q8*8+7

    const float4* hs4 = (const float4*)g_bufB;
    float4* out4 = (float4*)g_bufA;

    float4 b0 = make_float4(bias[q8 * 8 + 0], bias[q8 * 8 + 1], bias[q8 * 8 + 2], bias[q8 * 8 + 3]);
    float4 b1 = make_float4(bias[q8 * 8 + 4], bias[q8 * 8 + 5], bias[q8 * 8 + 6], bias[q8 * 8 + 7]);

    float s1[8] = {0, 0, 0, 0, 0, 0, 0, 0};
    float s2[8] = {0, 0, 0, 0, 0, 0, 0, 0};

    for (int node = gw; node < n; node += nw) {
        int rs = g_rowptr[node];
        int re = g_rowptr[node + 1];

        float4 acc0, acc1;
        if (qid == 0) {  // self-loop term
            acc0 = hs4[(size_t)node * HC + q8 * 2 + 0];
            acc1 = hs4[(size_t)node * HC + q8 * 2 + 1];
        } else {
            acc0 = make_float4(0, 0, 0, 0);
            acc1 = make_float4(0, 0, 0, 0);
        }

        int e2 = rs + qid;
        int idx = (e2 < re) ? g_csrsrc[e2] : 0;
        while (e2 < re) {
            int nxt = (e2 + 4 < re) ? g_csrsrc[e2 + 4] : 0;
            const float4* row = hs4 + (size_t)idx * HC + q8 * 2;
            float4 v0 = row[0];
            float4 v1 = row[1];
            acc0.x += v0.x; acc0.y += v0.y; acc0.z += v0.z; acc0.w += v0.w;
            acc1.x += v1.x; acc1.y += v1.y; acc1.z += v1.z; acc1.w += v1.w;
            idx = nxt;
            e2 += 4;
        }

        float vals[8] = {acc0.x, acc0.y, acc0.z, acc0.w, acc1.x, acc1.y, acc1.z, acc1.w};
        #pragma unroll
        for (int i = 0; i < 8; i++) {
            vals[i] += __shfl_xor_sync(0xffffffffu, vals[i], 8);
            vals[i] += __shfl_xor_sync(0xffffffffu, vals[i], 16);
        }

        if (qid == 0) {
            float dv = g_dinv[node];
            float4 y0, y1;
            y0.x = fmaf(vals[0], dv, b0.x); y0.y = fmaf(vals[1], dv, b0.y);
            y0.z = fmaf(vals[2], dv, b0.z); y0.w = fmaf(vals[3], dv, b0.w);
            y1.x = fmaf(vals[4], dv, b1.x); y1.y = fmaf(vals[5], dv, b1.y);
            y1.z = fmaf(vals[6], dv, b1.z); y1.w = fmaf(vals[7], dv, b1.w);
            out4[(size_t)node * HC + q8 * 2 + 0] = y0;
            out4[(size_t)node * HC + q8 * 2 + 1] = y1;
            float yv[8] = {y0.x, y0.y, y0.z, y0.w, y1.x, y1.y, y1.z, y1.w};
            #pragma unroll
            for (int i = 0; i < 8; i++) { s1[i] += yv[i]; s2[i] += yv[i] * yv[i]; }
        }
    }

    // block-level stat reduction, then one global atomic per column
    __shared__ float ssum[H], ssq[H];
    if (tid < H) { ssum[tid] = 0.f; ssq[tid] = 0.f; }
    __syncthreads();
    if (qid == 0) {
        int c0 = q8 * 8;
        #pragma unroll
        for (int i = 0; i < 8; i++) {
            atomicAdd(&ssum[c0 + i], s1[i]);
            atomicAdd(&ssq[c0 + i], s2[i]);
        }
    }
    __syncthreads();
    if (tid < H) {
        atomicAdd(&g_sum[layer * H + tid], ssum[tid]);
        atomicAdd(&g_sumsq[layer * H + tid], ssq[tid]);
    }
}

// ------------------------- pooling: segment mean over sorted batch -------------------------
__global__ void __launch_bounds__(256) pool_kernel(const int* __restrict__ batch,
                                                   const float* __restrict__ gamma,
                                                   const float* __restrict__ beta,
                                                   int n, float fn) {
    __shared__ float sScale[H], sShift[H];
    int tid = threadIdx.x;
    if (tid < H) {
        float m = g_sum[2 * H + tid] / fn;
        float var = g_sumsq[2 * H + tid] / fn - m * m;
        float inv = rsqrtf(var + EPS);
        float sc = inv * gamma[tid];
        sScale[tid] = sc;
        sShift[tid] = beta[tid] - m * sc;
    }
    __syncthreads();

    int g = blockIdx.x >> 3, sub = blockIdx.x & 7;
    int start, end;
    {
        int key = g;
        int lo = 0, hi = n;
        while (lo < hi) { int mid = (lo + hi) >> 1; if (batch[mid] < key) lo = mid + 1; else hi = mid; }
        start = lo;
        key = g + 1;
        lo = 0; hi = n;
        while (lo < hi) { int mid = (lo + hi) >> 1; if (batch[mid] < key) lo = mid + 1; else hi = mid; }
        end = lo;
    }
    int c = tid & 63;
    int rr = tid >> 6;  // 0..3
    float sc = sScale[c], sh = sShift[c];
    float cnt = fmaxf((float)(end - start), 1.f);
    float s = 0.f;
    for (int row = start + sub * 4 + rr; row < end; row += 32)
        s += fmaxf(fmaf(g_bufA[(size_t)row * H + c], sc, sh), 0.f);

    __shared__ float sm[256];
    sm[tid] = s;
    __syncthreads();
    if (tid < 128) sm[tid] += sm[tid + 128];
    __syncthreads();
    if (tid < 64) atomicAdd(&g_pool[g * H + tid], (sm[tid] + sm[tid + 64]) / cnt);
}

// ------------------------- final MLP -------------------------
__global__ void mlp_kernel(const float* __restrict__ l1w, const float* __restrict__ l1b,
                           const float* __restrict__ l2w, const float* __restrict__ l2b,
                           float* __restrict__ out) {
    int g = blockIdx.x, j = threadIdx.x;  // 32 threads
    __shared__ float p[H];
    p[j]      = g_pool[g * H + j];
    p[j + 32] = g_pool[g * H + j + 32];
    __syncwarp();
    float h = l1b[j];
    #pragma unroll
    for (int k = 0; k < H; k++) h = fmaf(p[k], l1w[j * H + k], h);
    h = fmaxf(h, 0.f);
    float v = h * l2w[j];
    #pragma unroll
    for (int o = 16; o; o >>= 1) v += __shfl_xor_sync(0xffffffffu, v, o);
    if (j == 0) out[g] = v + l2b[0];
}

// ------------------------- host launcher -------------------------
extern "C" void kernel_launch(void* const* d_in, const int* in_sizes, int n_in,
                              void* d_out, int out_size) {
    const float* x     = (const float*)d_in[0];
    const int*   ei    = (const int*)d_in[1];     // int32 on device (JAX x64 disabled)
    const int*   batch = (const int*)d_in[2];
    const float* W0  = (const float*)d_in[3];
    const float* b0  = (const float*)d_in[4];
    const float* gm0 = (const float*)d_in[5];
    const float* be0 = (const float*)d_in[6];
    const float* W1  = (const float*)d_in[7];
    const float* b1  = (const float*)d_in[8];
    const float* gm1 = (const float*)d_in[9];
    const float* be1 = (const float*)d_in[10];
    const float* W2  = (const float*)d_in[11];
    const float* b2  = (const float*)d_in[12];
    const float* gm2 = (const float*)d_in[13];
    const float* be2 = (const float*)d_in[14];
    const float* l1w = (const float*)d_in[15];
    const float* l1b = (const float*)d_in[16];
    const float* l2w = (const float*)d_in[17];
    const float* l2b = (const float*)d_in[18];

    int n = in_sizes[0] / 128;     // nodes
    int e = in_sizes[1] / 2;       // edges
    int G = out_size;              // graphs (64)

    // CSR build (coalesced 3-kernel scan — fused single-block version was a 90us regression)
    zero_all_kernel<<<(n + 255) / 256, 256>>>(n);
    hist_kernel<<<(e + 255) / 256, 256>>>(ei, e);
    int nb = (n + 1023) / 1024;
    scanA_kernel<<<nb, 1024>>>(n);
    scanB_kernel<<<1, 1024>>>(nb);
    scanC_kernel<<<nb, 1024>>>(n, e);
    fill_csr_kernel<<<(e + 255) / 256, 256>>>(ei, e);

    int gemm_grid = (n + 31) / 32;
    float fn = (float)n;

    // Layer 0
    gemm_kernel<128, false, true><<<gemm_grid, 256>>>(x, W0, nullptr, nullptr, n, 0, fn);
    agg_kernel<<<1024, 256>>>(b0, n, 0);
    // Layer 1 (BN of layer-0 stats applied inline)
    gemm_kernel<64, true, false><<<gemm_grid, 256>>>(nullptr, W1, gm0, be0, n, 0, fn);
    agg_kernel<<<1024, 256>>>(b1, n, 1);
    // Layer 2
    gemm_kernel<64, true, false><<<gemm_grid, 256>>>(nullptr, W2, gm1, be1, n, 1, fn);
    agg_kernel<<<1024, 256>>>(b2, n, 2);

    // Pool (BN of layer-2 stats inline) + MLP
    pool_kernel<<<G * 8, 256>>>(batch, gm2, be2, n, fn);
    mlp_kernel<<<G, 32>>>(l1w, l1b, l2w, l2b, (float*)d_out);
}

// round 6
// speedup vs baseline: 1.4745x; 1.4745x over previous
#include <cuda_runtime.h>
#include <cuda_bf16.h>
#include <cstdint>

#define MAXN 50000
#define MAXE 800000
#define H 64
#define HC 16   // H/4 float4 chunks
#define EPS 1e-5f

// ------------------------- device scratch (no allocs allowed) -------------------------
__device__ __align__(256) float g_bufA[MAXN * H];   // layer output y (agg result)
__device__ __align__(256) float g_bufB[MAXN * H];   // hs = (act @ W^T) * dinv
__device__ int   g_degcnt[MAXN];
__device__ int   g_rowptr[MAXN + 1];
__device__ int   g_cursor[MAXN];
__device__ int   g_csrsrc[MAXE];
__device__ float g_dinv[MAXN];
__device__ float g_sum[3 * H];     // per-layer BN stats (zeroed each replay)
__device__ float g_sumsq[3 * H];
__device__ float g_pool[64 * H];
__device__ int   g_bsum[1024];

// ------------------------- utility kernels -------------------------
__global__ void zero_all_kernel(int n) {
    int i = blockIdx.x * blockDim.x + threadIdx.x;
    int stride = gridDim.x * blockDim.x;
    for (int t = i; t < n; t += stride) g_degcnt[t] = 0;
    if (i < 64 * H) g_pool[i] = 0.f;
    if (i < 3 * H) { g_sum[i] = 0.f; g_sumsq[i] = 0.f; }
}

__global__ void hist_kernel(const int* __restrict__ ei, int e) {
    int i = blockIdx.x * blockDim.x + threadIdx.x;
    int stride = gridDim.x * blockDim.x;
    for (int t = i; t < e; t += stride) {
        int dst = ei[e + t];
        atomicAdd(&g_degcnt[dst], 1);
    }
}

// block-wide inclusive scan for 1024 threads
__device__ __forceinline__ int block_incl_scan(int v, int tid) {
    __shared__ int ws[32];
    int lane = tid & 31, w = tid >> 5;
    #pragma unroll
    for (int o = 1; o < 32; o <<= 1) {
        int t = __shfl_up_sync(0xffffffffu, v, o);
        if (lane >= o) v += t;
    }
    if (lane == 31) ws[w] = v;
    __syncthreads();
    if (w == 0) {
        int s = ws[lane];
        #pragma unroll
        for (int o = 1; o < 32; o <<= 1) {
            int t = __shfl_up_sync(0xffffffffu, s, o);
            if (lane >= o) s += t;
        }
        ws[lane] = s;
    }
    __syncthreads();
    return v + (w > 0 ? ws[w - 1] : 0);
}

__global__ void scanA_kernel(int n) {
    int tid = threadIdx.x;
    int gid = blockIdx.x * 1024 + tid;
    int v = (gid < n) ? g_degcnt[gid] : 0;
    int incl = block_incl_scan(v, tid);
    if (gid < n) g_rowptr[gid] = incl - v;   // exclusive within block
    if (tid == 1023) g_bsum[blockIdx.x] = incl;
}

__global__ void scanB_kernel(int nb) {
    int tid = threadIdx.x;
    int v = (tid < nb) ? g_bsum[tid] : 0;
    int incl = block_incl_scan(v, tid);
    if (tid < nb) g_bsum[tid] = incl - v;    // exclusive block offsets
}

__global__ void scanC_kernel(int n, int e) {
    int tid = threadIdx.x;
    int gid = blockIdx.x * 1024 + tid;
    if (gid < n) {
        int r = g_rowptr[gid] + g_bsum[blockIdx.x];
        g_rowptr[gid] = r;
        g_cursor[gid] = r;
        g_dinv[gid] = rsqrtf((float)g_degcnt[gid] + 1.0f);
    }
    if (gid == 0) g_rowptr[n] = e;
}

__global__ void fill_csr_kernel(const int* __restrict__ ei, int e) {
    int i = blockIdx.x * blockDim.x + threadIdx.x;
    int stride = gridDim.x * blockDim.x;
    for (int t = i; t < e; t += stride) {
        int s = ei[t];
        int d = ei[e + t];
        int pos = atomicAdd(&g_cursor[d], 1);
        g_csrsrc[pos] = s;
    }
}

// ------------------------- GEMM: hs = act @ W^T, scaled by dinv -------------------------
// Block = 256 threads = 8 warps, each warp computes 4 rows x 64 cols.
// W stored transposed in smem (stride 65, conflict-free).
// BN: input element = relu(in*scale[k]+shift[k]); scale/shift computed inline from
// per-layer stats (replaces the separate finalize kernel).
template <int K, bool BN, bool FROMX>
__global__ void __launch_bounds__(256) gemm_kernel(const float* __restrict__ in,
                                                   const float* __restrict__ W,
                                                   const float* __restrict__ gamma,
                                                   const float* __restrict__ beta,
                                                   int n, int layer, float fn) {
    __shared__ float Wsm[K * 65];
    __shared__ float sScale[H], sShift[H];
    int tid = threadIdx.x;
    for (int idx = tid; idx < H * K; idx += 256) {
        int o = idx / K, k = idx - o * K;
        Wsm[k * 65 + o] = W[idx];
    }
    if (BN && tid < H) {
        float m = g_sum[layer * H + tid] / fn;
        float var = g_sumsq[layer * H + tid] / fn - m * m;
        float inv = rsqrtf(var + EPS);
        float sc = inv * gamma[tid];
        sScale[tid] = sc;
        sShift[tid] = beta[tid] - m * sc;
    }
    __syncthreads();

    const float* src = FROMX ? in : g_bufA;

    int warp = tid >> 5, lane = tid & 31;
    int row0 = (blockIdx.x * 8 + warp) * 4;

    constexpr int J = K / 32;
    float a[4][J];
    #pragma unroll
    for (int r = 0; r < 4; r++) {
        int row = row0 + r;
        #pragma unroll
        for (int j = 0; j < J; j++) {
            int k = lane + 32 * j;
            float v = 0.f;
            if (row < n) {
                v = src[(size_t)row * K + k];
                if (BN) v = fmaxf(fmaf(v, sScale[k], sShift[k]), 0.f);
            }
            a[r][j] = v;
        }
    }

    float acc[4][2];
    #pragma unroll
    for (int r = 0; r < 4; r++) { acc[r][0] = 0.f; acc[r][1] = 0.f; }

    #pragma unroll
    for (int j = 0; j < J; j++) {
        #pragma unroll
        for (int ks = 0; ks < 32; ks++) {
            int kk = j * 32 + ks;
            float w0 = Wsm[kk * 65 + lane];
            float w1 = Wsm[kk * 65 + lane + 32];
            #pragma unroll
            for (int r = 0; r < 4; r++) {
                float av = __shfl_sync(0xffffffffu, a[r][j], ks);
                acc[r][0] = fmaf(av, w0, acc[r][0]);
                acc[r][1] = fmaf(av, w1, acc[r][1]);
            }
        }
    }

    #pragma unroll
    for (int r = 0; r < 4; r++) {
        int row = row0 + r;
        if (row < n) {
            float dv = g_dinv[row];
            g_bufB[(size_t)row * H + lane]      = acc[r][0] * dv;
            g_bufB[(size_t)row * H + lane + 32] = acc[r][1] * dv;
        }
    }
}

// ------------------------- Aggregation (R3 structure): y = dinv*(sum_nbr hs + hs_self) + bias
// Warp per node; two half-warp edge streams; 16 lanes x float4 = 64-float row.
// Fused: bias add, write y, BN statistics accumulation into per-layer slot.
__global__ void __launch_bounds__(256) agg_kernel(const float* __restrict__ bias,
                                                  int n, int layer) {
    int tid = threadIdx.x;
    int gw = (blockIdx.x * blockDim.x + tid) >> 5;
    int nw = (gridDim.x * blockDim.x) >> 5;
    int lane = tid & 31, half = lane >> 4, q = lane & 15;

    const float4* hs4 = (const float4*)g_bufB;
    float4* out4 = (float4*)g_bufA;

    float4 s1 = make_float4(0, 0, 0, 0);
    float4 s2 = make_float4(0, 0, 0, 0);
    float4 b4 = make_float4(bias[q * 4], bias[q * 4 + 1], bias[q * 4 + 2], bias[q * 4 + 3]);

    for (int node = gw; node < n; node += nw) {
        int rs = g_rowptr[node];
        int re = g_rowptr[node + 1];
        float4 acc;
        if (half == 0) acc = hs4[(size_t)node * HC + q];   // self-loop term
        else           acc = make_float4(0, 0, 0, 0);
        for (int e2 = rs + half; e2 < re; e2 += 2) {
            int src = g_csrsrc[e2];
            float4 v = hs4[(size_t)src * HC + q];
            acc.x += v.x; acc.y += v.y; acc.z += v.z; acc.w += v.w;
        }
        acc.x += __shfl_xor_sync(0xffffffffu, acc.x, 16);
        acc.y += __shfl_xor_sync(0xffffffffu, acc.y, 16);
        acc.z += __shfl_xor_sync(0xffffffffu, acc.z, 16);
        acc.w += __shfl_xor_sync(0xffffffffu, acc.w, 16);
        if (half == 0) {
            float dv = g_dinv[node];
            float4 y;
            y.x = fmaf(acc.x, dv, b4.x);
            y.y = fmaf(acc.y, dv, b4.y);
            y.z = fmaf(acc.z, dv, b4.z);
            y.w = fmaf(acc.w, dv, b4.w);
            out4[(size_t)node * HC + q] = y;
            s1.x += y.x; s1.y += y.y; s1.z += y.z; s1.w += y.w;
            s2.x += y.x * y.x; s2.y += y.y * y.y; s2.z += y.z * y.z; s2.w += y.w * y.w;
        }
    }

    __shared__ float ssum[H], ssq[H];
    if (tid < H) { ssum[tid] = 0.f; ssq[tid] = 0.f; }
    __syncthreads();
    if (half == 0) {
        int c0 = q * 4;
        atomicAdd(&ssum[c0 + 0], s1.x); atomicAdd(&ssum[c0 + 1], s1.y);
        atomicAdd(&ssum[c0 + 2], s1.z); atomicAdd(&ssum[c0 + 3], s1.w);
        atomicAdd(&ssq[c0 + 0], s2.x);  atomicAdd(&ssq[c0 + 1], s2.y);
        atomicAdd(&ssq[c0 + 2], s2.z);  atomicAdd(&ssq[c0 + 3], s2.w);
    }
    __syncthreads();
    if (tid < H) {
        atomicAdd(&g_sum[layer * H + tid], ssum[tid]);
        atomicAdd(&g_sumsq[layer * H + tid], ssq[tid]);
    }
}

// ------------------------- pooling: segment mean over sorted batch -------------------------
// 8 blocks per graph; binary search boundaries; BN(layer2)+ReLU applied on the fly.
__global__ void __launch_bounds__(256) pool_kernel(const int* __restrict__ batch,
                                                   const float* __restrict__ gamma,
                                                   const float* __restrict__ beta,
                                                   int n, float fn) {
    __shared__ float sScale[H], sShift[H];
    int tid = threadIdx.x;
    if (tid < H) {
        float m = g_sum[2 * H + tid] / fn;
        float var = g_sumsq[2 * H + tid] / fn - m * m;
        float inv = rsqrtf(var + EPS);
        float sc = inv * gamma[tid];
        sScale[tid] = sc;
        sShift[tid] = beta[tid] - m * sc;
    }
    __syncthreads();

    int g = blockIdx.x >> 3, sub = blockIdx.x & 7;
    int start, end;
    {
        int key = g;
        int lo = 0, hi = n;
        while (lo < hi) { int mid = (lo + hi) >> 1; if (batch[mid] < key) lo = mid + 1; else hi = mid; }
        start = lo;
        key = g + 1;
        lo = 0; hi = n;
        while (lo < hi) { int mid = (lo + hi) >> 1; if (batch[mid] < key) lo = mid + 1; else hi = mid; }
        end = lo;
    }
    int c = tid & 63;
    int rr = tid >> 6;  // 0..3
    float sc = sScale[c], sh = sShift[c];
    float cnt = fmaxf((float)(end - start), 1.f);
    float s = 0.f;
    for (int row = start + sub * 4 + rr; row < end; row += 32)
        s += fmaxf(fmaf(g_bufA[(size_t)row * H + c], sc, sh), 0.f);

    __shared__ float sm[256];
    sm[tid] = s;
    __syncthreads();
    if (tid < 128) sm[tid] += sm[tid + 128];
    __syncthreads();
    if (tid < 64) atomicAdd(&g_pool[g * H + tid], (sm[tid] + sm[tid + 64]) / cnt);
}

// ------------------------- final MLP -------------------------
__global__ void mlp_kernel(const float* __restrict__ l1w, const float* __restrict__ l1b,
                           const float* __restrict__ l2w, const float* __restrict__ l2b,
                           float* __restrict__ out) {
    int g = blockIdx.x, j = threadIdx.x;  // 32 threads
    __shared__ float p[H];
    p[j]      = g_pool[g * H + j];
    p[j + 32] = g_pool[g * H + j + 32];
    __syncwarp();
    float h = l1b[j];
    #pragma unroll
    for (int k = 0; k < H; k++) h = fmaf(p[k], l1w[j * H + k], h);
    h = fmaxf(h, 0.f);
    float v = h * l2w[j];
    #pragma unroll
    for (int o = 16; o; o >>= 1) v += __shfl_xor_sync(0xffffffffu, v, o);
    if (j == 0) out[g] = v + l2b[0];
}

// ------------------------- host launcher -------------------------
extern "C" void kernel_launch(void* const* d_in, const int* in_sizes, int n_in,
                              void* d_out, int out_size) {
    const float* x     = (const float*)d_in[0];
    const int*   ei    = (const int*)d_in[1];     // int32 on device (JAX x64 disabled)
    const int*   batch = (const int*)d_in[2];
    const float* W0  = (const float*)d_in[3];
    const float* b0  = (const float*)d_in[4];
    const float* gm0 = (const float*)d_in[5];
    const float* be0 = (const float*)d_in[6];
    const float* W1  = (const float*)d_in[7];
    const float* b1  = (const float*)d_in[8];
    const float* gm1 = (const float*)d_in[9];
    const float* be1 = (const float*)d_in[10];
    const float* W2  = (const float*)d_in[11];
    const float* b2  = (const float*)d_in[12];
    const float* gm2 = (const float*)d_in[13];
    const float* be2 = (const float*)d_in[14];
    const float* l1w = (const float*)d_in[15];
    const float* l1b = (const float*)d_in[16];
    const float* l2w = (const float*)d_in[17];
    const float* l2b = (const float*)d_in[18];

    int n = in_sizes[0] / 128;     // nodes
    int e = in_sizes[1] / 2;       // edges
    int G = out_size;              // graphs (64)

    // CSR build (coalesced 3-kernel scan)
    zero_all_kernel<<<(n + 255) / 256, 256>>>(n);
    hist_kernel<<<(e + 255) / 256, 256>>>(ei, e);
    int nb = (n + 1023) / 1024;
    scanA_kernel<<<nb, 1024>>>(n);
    scanB_kernel<<<1, 1024>>>(nb);
    scanC_kernel<<<nb, 1024>>>(n, e);
    fill_csr_kernel<<<(e + 255) / 256, 256>>>(ei, e);

    int gemm_grid = (n + 31) / 32;
    float fn = (float)n;

    // Layer 0
    gemm_kernel<128, false, true><<<gemm_grid, 256>>>(x, W0, nullptr, nullptr, n, 0, fn);
    agg_kernel<<<512, 256>>>(b0, n, 0);
    // Layer 1 (BN of layer-0 stats applied inline)
    gemm_kernel<64, true, false><<<gemm_grid, 256>>>(nullptr, W1, gm0, be0, n, 0, fn);
    agg_kernel<<<512, 256>>>(b1, n, 1);
    // Layer 2
    gemm_kernel<64, true, false><<<gemm_grid, 256>>>(nullptr, W2, gm1, be1, n, 1, fn);
    agg_kernel<<<512, 256>>>(b2, n, 2);

    // Pool (BN of layer-2 stats inline) + MLP
    pool_kernel<<<G * 8, 256>>>(batch, gm2, be2, n, fn);
    mlp_kernel<<<G, 32>>>(l1w, l1b, l2w, l2b, (float*)d_out);
}